// round 10
// baseline (speedup 1.0000x reference)
#include <cuda_runtime.h>
#include <cuda_fp16.h>
#include <cstdint>

// ---------------- problem constants ----------------
#define NB    16
#define NSEQ  65536
#define CIN   256
#define COUT  256
#define RANK  10

#define CTAS_PER_BATCH 9
#define GRID_MAIN (NB * CTAS_PER_BATCH)     // 144
#define NTHREADS  256                        // 8 warps: 2 (M) x 4 (N)
#define TILES_PER_BATCH (NSEQ / 128)         // 512
#define NCHUNK 4                             // K chunks of 64

// ---------------- SMEM map (dynamic, padded rows, NO swizzle) ----------------
// Row stride 144 bytes (= 128 data + 16 pad). 144 % 16 == 0 so every ldmatrix
// address stays 16B aligned; consecutive rows step shared banks by +4, so the
// 8 rows of one ldmatrix phase cover all 32 banks exactly once (conflict-free).
#define ROWB  144
#define SM_FS   0u          // 256 floats
#define SM_PH   1024u       // 256 floats
#define SM_A    4096u       // 2 x (128*144 = 18432)
#define A_BUF   18432u
#define SM_B    40960u      // 4 x (256*144 = 36864)
#define B_BUF   36864u
#define SMEM_TOTAL 188416

__device__ __align__(16) __half g_W[NB * COUT * CIN];   // 2 MB scratch (W' fp16)

// ---------------- helpers ----------------
__device__ __forceinline__ uint32_t smem_u32(const void* p) {
    uint32_t a;
    asm("{ .reg .u64 t; cvta.to.shared.u64 t, %1; cvt.u32.u64 %0, t; }" : "=r"(a) : "l"(p));
    return a;
}

__device__ __forceinline__ void ldsm4(uint32_t& r0, uint32_t& r1, uint32_t& r2, uint32_t& r3,
                                      uint32_t addr) {
    asm volatile("ldmatrix.sync.aligned.m8n8.x4.shared.b16 {%0,%1,%2,%3}, [%4];"
                 : "=r"(r0), "=r"(r1), "=r"(r2), "=r"(r3) : "r"(addr));
}

__device__ __forceinline__ void mma16816(float* d, uint32_t a0, uint32_t a1, uint32_t a2,
                                         uint32_t a3, uint32_t b0, uint32_t b1) {
    asm volatile(
        "mma.sync.aligned.m16n8k16.row.col.f32.f16.f16.f32 "
        "{%0,%1,%2,%3}, {%4,%5,%6,%7}, {%8,%9}, {%0,%1,%2,%3};"
        : "+f"(d[0]), "+f"(d[1]), "+f"(d[2]), "+f"(d[3])
        : "r"(a0), "r"(a1), "r"(a2), "r"(a3), "r"(b0), "r"(b1));
}

// ------------- prep: W'[b,o,i] = weight[o,i]*(sigmoid(L.R/sqrt(10))+0.5) -------------
__global__ void __launch_bounds__(CIN) fmm_prep(const float* __restrict__ freq,
                                               const float* __restrict__ weight) {
    int bo = blockIdx.x;
    int b = bo >> 8;
    int o = bo & 255;
    int i = threadIdx.x;
    __shared__ float lsh[RANK];
    const float* fb = freq + (size_t)b * (RANK * (CIN + COUT));
    if (i < RANK) lsh[i] = fb[o * RANK + i];
    __syncthreads();
    const float* right = fb + COUT * RANK;   // [RANK, CIN]
    float acc = 0.f;
#pragma unroll
    for (int r = 0; r < RANK; r++) acc = fmaf(lsh[r], right[r * CIN + i], acc);
    acc *= 0.31622776601683794f;             // 1/sqrt(10)
    float sig = 1.0f / (1.0f + __expf(-acc));
    float w = weight[o * CIN + i] * (sig + 0.5f);
    g_W[(size_t)(b * COUT + o) * CIN + i] = __float2half_rn(w);
}

// ------------- main: persistent batched fp16 HMMA GEMM + sin epilogue -------------
__global__ void __launch_bounds__(NTHREADS, 1)
fmm_main(const float* __restrict__ x,
         const float* __restrict__ phase_shift,
         float* __restrict__ out) {
    extern __shared__ __align__(1024) char smem[];
    uint32_t sb = smem_u32(smem);
    int tid  = threadIdx.x;
    int wid  = tid >> 5;
    int lane = tid & 31;
    int wm   = wid >> 2;        // 0..1   (M direction, 64 rows each)
    int wn   = wid & 3;         // 0..3   (N direction, 64 cols each)

    int cta = blockIdx.x;
    int b   = cta / CTAS_PER_BATCH;
    int sub = cta % CTAS_PER_BATCH;

    // per-batch sin params
    {
        float f = phase_shift[(size_t)b * (2 * COUT) + tid];
        float p = (phase_shift[(size_t)b * (2 * COUT) + COUT + tid] - 30.0f) * (1.0f / 15.0f);
        *(float*)(smem + SM_FS + tid * 4) = f;
        *(float*)(smem + SM_PH + tid * 4) = p;
    }

    // B = W' fp16 into padded SMEM: 4 K-chunks, each [256 rows(n) x 64 halves(k)]
    {
        const __half* Wb = g_W + (size_t)b * COUT * CIN;
        for (int it = tid; it < 8192; it += NTHREADS) {
            int o = it >> 5;                  // 0..255 (n)
            int i = (it & 31) * 8;            // 0..248 (k), 8 halves
            uint4 v = *reinterpret_cast<const uint4*>(Wb + (size_t)o * CIN + i);
            int c  = i >> 6;
            int kk = i & 63;
            uint32_t off = SM_B + (uint32_t)c * B_BUF + (uint32_t)o * ROWB + (uint32_t)kk * 2;
            *reinterpret_cast<uint4*>(smem + off) = v;
        }
    }
    __syncthreads();

    // ldmatrix lane address components: lanes 0-15 -> rows 0..15 (k-lo half),
    // lanes 16-31 -> rows 0..15 at k+8
    int row16 = lane & 15;
    int koff  = (lane >> 4) << 3;             // 0 or 8 (halves)

    float4 stage[8];                          // staged fp32 x loads for next chunk

    auto ldg_chunk = [&](int t, int c) {
        const float* src = x + ((size_t)b * NSEQ + (size_t)t * 128) * CIN + c * 64;
#pragma unroll
        for (int j = 0; j < 8; j++) {
            int v  = j * 256 + tid;           // 0..2047
            int m  = v >> 4;                  // row 0..127
            int k4 = (v & 15) * 4;            // 0..60
            stage[j] = __ldcs(reinterpret_cast<const float4*>(src + (size_t)m * CIN + k4));
        }
    };

    // preload first chunk
    ldg_chunk(sub, 0);

    for (int t = sub; t < TILES_PER_BATCH; t += CTAS_PER_BATCH) {
        float acc[4][8][4];
#pragma unroll
        for (int mi = 0; mi < 4; mi++)
#pragma unroll
            for (int ni = 0; ni < 8; ni++)
#pragma unroll
                for (int q = 0; q < 4; q++) acc[mi][ni][q] = 0.f;

#pragma unroll 1
        for (int c = 0; c < NCHUNK; c++) {
            // convert staged fp32 -> fp16, store into A buffer c&1
            uint32_t abase = SM_A + (uint32_t)(c & 1) * A_BUF;
#pragma unroll
            for (int j = 0; j < 8; j++) {
                int v  = j * 256 + tid;
                int m  = v >> 4;
                int k4 = (v & 15) * 4;
                __half2 h0 = __floats2half2_rn(stage[j].x, stage[j].y);
                __half2 h1 = __floats2half2_rn(stage[j].z, stage[j].w);
                uint2 pkt;
                pkt.x = *reinterpret_cast<uint32_t*>(&h0);
                pkt.y = *reinterpret_cast<uint32_t*>(&h1);
                uint32_t off = abase + (uint32_t)m * ROWB + (uint32_t)k4 * 2;
                *reinterpret_cast<uint2*>(smem + off) = pkt;
            }
            __syncthreads();

            // prefetch next chunk (possibly next tile's chunk 0)
            {
                int nc = c + 1, nt = t;
                if (nc == NCHUNK) { nc = 0; nt = t + CTAS_PER_BATCH; }
                if (nt < TILES_PER_BATCH) ldg_chunk(nt, nc);
            }

            // compute this chunk: 4 k16 steps
            uint32_t a_sb = sb + abase;
            uint32_t b_sb = sb + SM_B + (uint32_t)c * B_BUF;
#pragma unroll
            for (int ks = 0; ks < 4; ks++) {
                uint32_t a[4][4], bf[4][4];
                uint32_t kb = (uint32_t)((ks * 16 + koff) * 2);
#pragma unroll
                for (int mi = 0; mi < 4; mi++) {
                    uint32_t ad = a_sb + (uint32_t)(wm * 64 + mi * 16 + row16) * ROWB + kb;
                    ldsm4(a[mi][0], a[mi][1], a[mi][2], a[mi][3], ad);
                }
#pragma unroll
                for (int ng = 0; ng < 4; ng++) {
                    uint32_t bd = b_sb + (uint32_t)(wn * 64 + ng * 16 + row16) * ROWB + kb;
                    ldsm4(bf[ng][0], bf[ng][1], bf[ng][2], bf[ng][3], bd);
                }
#pragma unroll
                for (int mi = 0; mi < 4; mi++)
#pragma unroll
                    for (int ni = 0; ni < 8; ni++) {
                        int ng = ni >> 1;
                        uint32_t b0, b1;
                        if ((ni & 1) == 0) { b0 = bf[ng][0]; b1 = bf[ng][2]; }
                        else               { b0 = bf[ng][1]; b1 = bf[ng][3]; }
                        mma16816(acc[mi][ni], a[mi][0], a[mi][1], a[mi][2], a[mi][3], b0, b1);
                    }
            }
            __syncthreads();
        }

        // -------- sin epilogue straight from fragments --------
        size_t rowbase = (size_t)b * NSEQ + (size_t)t * 128;
#pragma unroll
        for (int ni = 0; ni < 8; ni++) {
            int col = wn * 64 + ni * 8 + (lane & 3) * 2;
            float2 fs2 = *(float2*)(smem + SM_FS + col * 4);
            float2 ph2 = *(float2*)(smem + SM_PH + col * 4);
#pragma unroll
            for (int mi = 0; mi < 4; mi++) {
                int r0 = wm * 64 + mi * 16 + (lane >> 2);
                float2 o0, o1;
                o0.x = __sinf(fmaf(fs2.x, acc[mi][ni][0], ph2.x));
                o0.y = __sinf(fmaf(fs2.y, acc[mi][ni][1], ph2.y));
                o1.x = __sinf(fmaf(fs2.x, acc[mi][ni][2], ph2.x));
                o1.y = __sinf(fmaf(fs2.y, acc[mi][ni][3], ph2.y));
                *reinterpret_cast<float2*>(out + (rowbase + r0) * COUT + col)     = o0;
                *reinterpret_cast<float2*>(out + (rowbase + r0 + 8) * COUT + col) = o1;
            }
        }
    }
}

extern "C" void kernel_launch(void* const* d_in, const int* in_sizes, int n_in,
                              void* d_out, int out_size) {
    const float* x    = (const float*)d_in[0];
    const float* freq = (const float*)d_in[1];
    const float* ps   = (const float*)d_in[2];
    const float* w    = (const float*)d_in[3];
    float* out = (float*)d_out;

    cudaFuncSetAttribute(fmm_main, cudaFuncAttributeMaxDynamicSharedMemorySize, SMEM_TOTAL);

    fmm_prep<<<NB * COUT, CIN>>>(freq, w);
    fmm_main<<<GRID_MAIN, NTHREADS, SMEM_TOTAL>>>(x, ps, out);
}

// round 11
// speedup vs baseline: 1.0026x; 1.0026x over previous
#include <cuda_runtime.h>
#include <cuda_fp16.h>
#include <cstdint>

// ---------------- problem constants ----------------
#define NB    16
#define NSEQ  65536
#define CIN   256
#define COUT  256
#define RANK  10

#define CTAS_PER_BATCH 9
#define GRID_MAIN (NB * CTAS_PER_BATCH)     // 144
#define NTHREADS  256                        // 8 warps: 2 (M) x 4 (N)
#define TILES_PER_BATCH (NSEQ / 128)         // 512
#define NCHUNK 4                             // K chunks of 64

// ---------------- SMEM map (dynamic, padded rows, NO swizzle) ----------------
// Row stride 144 bytes (= 128 data + 16 pad). 144 % 16 == 0 so every ldmatrix
// address stays 16B aligned; consecutive rows step shared banks by +4, so the
// 8 rows of one ldmatrix phase cover all 32 banks exactly once (conflict-free).
#define ROWB  144
#define SM_FS   0u          // 256 floats
#define SM_PH   1024u       // 256 floats
#define SM_A    4096u       // 2 x (128*144 = 18432)
#define A_BUF   18432u
#define SM_B    40960u      // 4 x (256*144 = 36864)
#define B_BUF   36864u
#define SMEM_TOTAL 188416

__device__ __align__(16) __half g_W[NB * COUT * CIN];   // 2 MB scratch (W' fp16)

// ---------------- helpers ----------------
__device__ __forceinline__ uint32_t smem_u32(const void* p) {
    uint32_t a;
    asm("{ .reg .u64 t; cvta.to.shared.u64 t, %1; cvt.u32.u64 %0, t; }" : "=r"(a) : "l"(p));
    return a;
}

__device__ __forceinline__ void ldsm4(uint32_t& r0, uint32_t& r1, uint32_t& r2, uint32_t& r3,
                                      uint32_t addr) {
    asm volatile("ldmatrix.sync.aligned.m8n8.x4.shared.b16 {%0,%1,%2,%3}, [%4];"
                 : "=r"(r0), "=r"(r1), "=r"(r2), "=r"(r3) : "r"(addr));
}

__device__ __forceinline__ void mma16816(float* d, uint32_t a0, uint32_t a1, uint32_t a2,
                                         uint32_t a3, uint32_t b0, uint32_t b1) {
    asm volatile(
        "mma.sync.aligned.m16n8k16.row.col.f32.f16.f16.f32 "
        "{%0,%1,%2,%3}, {%4,%5,%6,%7}, {%8,%9}, {%0,%1,%2,%3};"
        : "+f"(d[0]), "+f"(d[1]), "+f"(d[2]), "+f"(d[3])
        : "r"(a0), "r"(a1), "r"(a2), "r"(a3), "r"(b0), "r"(b1));
}

// ------------- prep: W'[b,o,i] = weight[o,i]*(sigmoid(L.R/sqrt(10))+0.5) -------------
__global__ void __launch_bounds__(CIN) fmm_prep(const float* __restrict__ freq,
                                               const float* __restrict__ weight) {
    int bo = blockIdx.x;
    int b = bo >> 8;
    int o = bo & 255;
    int i = threadIdx.x;
    __shared__ float lsh[RANK];
    const float* fb = freq + (size_t)b * (RANK * (CIN + COUT));
    if (i < RANK) lsh[i] = fb[o * RANK + i];
    __syncthreads();
    const float* right = fb + COUT * RANK;   // [RANK, CIN]
    float acc = 0.f;
#pragma unroll
    for (int r = 0; r < RANK; r++) acc = fmaf(lsh[r], right[r * CIN + i], acc);
    acc *= 0.31622776601683794f;             // 1/sqrt(10)
    float sig = 1.0f / (1.0f + __expf(-acc));
    float w = weight[o * CIN + i] * (sig + 0.5f);
    g_W[(size_t)(b * COUT + o) * CIN + i] = __float2half_rn(w);
}

// ------------- main: persistent batched fp16 HMMA GEMM + sin epilogue -------------
__global__ void __launch_bounds__(NTHREADS, 1)
fmm_main(const float* __restrict__ x,
         const float* __restrict__ phase_shift,
         float* __restrict__ out) {
    extern __shared__ __align__(1024) char smem[];
    uint32_t sb = smem_u32(smem);
    int tid  = threadIdx.x;
    int wid  = tid >> 5;
    int lane = tid & 31;
    int wm   = wid >> 2;        // 0..1   (M direction, 64 rows each)
    int wn   = wid & 3;         // 0..3   (N direction, 64 cols each)

    int cta = blockIdx.x;
    int b   = cta / CTAS_PER_BATCH;
    int sub = cta % CTAS_PER_BATCH;

    // per-batch sin params
    {
        float f = phase_shift[(size_t)b * (2 * COUT) + tid];
        float p = (phase_shift[(size_t)b * (2 * COUT) + COUT + tid] - 30.0f) * (1.0f / 15.0f);
        *(float*)(smem + SM_FS + tid * 4) = f;
        *(float*)(smem + SM_PH + tid * 4) = p;
    }

    // B = W' fp16 into padded SMEM: 4 K-chunks, each [256 rows(n) x 64 halves(k)]
    {
        const __half* Wb = g_W + (size_t)b * COUT * CIN;
        for (int it = tid; it < 8192; it += NTHREADS) {
            int o = it >> 5;                  // 0..255 (n)
            int i = (it & 31) * 8;            // 0..248 (k), 8 halves
            uint4 v = *reinterpret_cast<const uint4*>(Wb + (size_t)o * CIN + i);
            int c  = i >> 6;
            int kk = i & 63;
            uint32_t off = SM_B + (uint32_t)c * B_BUF + (uint32_t)o * ROWB + (uint32_t)kk * 2;
            *reinterpret_cast<uint4*>(smem + off) = v;
        }
    }
    __syncthreads();

    // ldmatrix lane address components: lanes 0-15 -> rows 0..15 (k-lo half),
    // lanes 16-31 -> rows 0..15 at k+8
    int row16 = lane & 15;
    int koff  = (lane >> 4) << 3;             // 0 or 8 (halves)

    float4 stage[8];                          // staged fp32 x loads for next chunk

    auto ldg_chunk = [&](int t, int c) {
        const float* src = x + ((size_t)b * NSEQ + (size_t)t * 128) * CIN + c * 64;
#pragma unroll
        for (int j = 0; j < 8; j++) {
            int v  = j * 256 + tid;           // 0..2047
            int m  = v >> 4;                  // row 0..127
            int k4 = (v & 15) * 4;            // 0..60
            stage[j] = __ldcs(reinterpret_cast<const float4*>(src + (size_t)m * CIN + k4));
        }
    };

    // preload first chunk
    ldg_chunk(sub, 0);

    for (int t = sub; t < TILES_PER_BATCH; t += CTAS_PER_BATCH) {
        float acc[4][8][4];
#pragma unroll
        for (int mi = 0; mi < 4; mi++)
#pragma unroll
            for (int ni = 0; ni < 8; ni++)
#pragma unroll
                for (int q = 0; q < 4; q++) acc[mi][ni][q] = 0.f;

#pragma unroll 1
        for (int c = 0; c < NCHUNK; c++) {
            // convert staged fp32 -> fp16, store into A buffer c&1
            uint32_t abase = SM_A + (uint32_t)(c & 1) * A_BUF;
#pragma unroll
            for (int j = 0; j < 8; j++) {
                int v  = j * 256 + tid;
                int m  = v >> 4;
                int k4 = (v & 15) * 4;
                __half2 h0 = __floats2half2_rn(stage[j].x, stage[j].y);
                __half2 h1 = __floats2half2_rn(stage[j].z, stage[j].w);
                uint2 pkt;
                pkt.x = *reinterpret_cast<uint32_t*>(&h0);
                pkt.y = *reinterpret_cast<uint32_t*>(&h1);
                uint32_t off = abase + (uint32_t)m * ROWB + (uint32_t)k4 * 2;
                *reinterpret_cast<uint2*>(smem + off) = pkt;
            }
            __syncthreads();

            // prefetch next chunk (possibly next tile's chunk 0)
            {
                int nc = c + 1, nt = t;
                if (nc == NCHUNK) { nc = 0; nt = t + CTAS_PER_BATCH; }
                if (nt < TILES_PER_BATCH) ldg_chunk(nt, nc);
            }

            // compute this chunk: 4 k16 steps
            uint32_t a_sb = sb + abase;
            uint32_t b_sb = sb + SM_B + (uint32_t)c * B_BUF;
#pragma unroll
            for (int ks = 0; ks < 4; ks++) {
                uint32_t a[4][4], bf[4][4];
                uint32_t kb = (uint32_t)((ks * 16 + koff) * 2);
#pragma unroll
                for (int mi = 0; mi < 4; mi++) {
                    uint32_t ad = a_sb + (uint32_t)(wm * 64 + mi * 16 + row16) * ROWB + kb;
                    ldsm4(a[mi][0], a[mi][1], a[mi][2], a[mi][3], ad);
                }
#pragma unroll
                for (int ng = 0; ng < 4; ng++) {
                    uint32_t bd = b_sb + (uint32_t)(wn * 64 + ng * 16 + row16) * ROWB + kb;
                    ldsm4(bf[ng][0], bf[ng][1], bf[ng][2], bf[ng][3], bd);
                }
#pragma unroll
                for (int mi = 0; mi < 4; mi++)
#pragma unroll
                    for (int ni = 0; ni < 8; ni++) {
                        int ng = ni >> 1;
                        uint32_t b0, b1;
                        if ((ni & 1) == 0) { b0 = bf[ng][0]; b1 = bf[ng][2]; }
                        else               { b0 = bf[ng][1]; b1 = bf[ng][3]; }
                        mma16816(acc[mi][ni], a[mi][0], a[mi][1], a[mi][2], a[mi][3], b0, b1);
                    }
            }
            __syncthreads();
        }

        // -------- sin epilogue straight from fragments --------
        size_t rowbase = (size_t)b * NSEQ + (size_t)t * 128;
#pragma unroll
        for (int ni = 0; ni < 8; ni++) {
            int col = wn * 64 + ni * 8 + (lane & 3) * 2;
            float2 fs2 = *(float2*)(smem + SM_FS + col * 4);
            float2 ph2 = *(float2*)(smem + SM_PH + col * 4);
#pragma unroll
            for (int mi = 0; mi < 4; mi++) {
                int r0 = wm * 64 + mi * 16 + (lane >> 2);
                float2 o0, o1;
                o0.x = __sinf(fmaf(fs2.x, acc[mi][ni][0], ph2.x));
                o0.y = __sinf(fmaf(fs2.y, acc[mi][ni][1], ph2.y));
                o1.x = __sinf(fmaf(fs2.x, acc[mi][ni][2], ph2.x));
                o1.y = __sinf(fmaf(fs2.y, acc[mi][ni][3], ph2.y));
                *reinterpret_cast<float2*>(out + (rowbase + r0) * COUT + col)     = o0;
                *reinterpret_cast<float2*>(out + (rowbase + r0 + 8) * COUT + col) = o1;
            }
        }
    }
}

extern "C" void kernel_launch(void* const* d_in, const int* in_sizes, int n_in,
                              void* d_out, int out_size) {
    const float* x    = (const float*)d_in[0];
    const float* freq = (const float*)d_in[1];
    const float* ps   = (const float*)d_in[2];
    const float* w    = (const float*)d_in[3];
    float* out = (float*)d_out;

    cudaFuncSetAttribute(fmm_main, cudaFuncAttributeMaxDynamicSharedMemorySize, SMEM_TOTAL);

    fmm_prep<<<NB * COUT, CIN>>>(freq, w);
    fmm_main<<<GRID_MAIN, NTHREADS, SMEM_TOTAL>>>(x, ps, out);
}

// round 12
// speedup vs baseline: 1.0219x; 1.0193x over previous
#include <cuda_runtime.h>
#include <cuda_fp16.h>
#include <cstdint>

// ---------------- problem constants ----------------
#define NB    16
#define NSEQ  65536
#define CIN   256
#define COUT  256
#define RANK  10

#define CTAS_PER_BATCH 9
#define GRID_MAIN (NB * CTAS_PER_BATCH)     // 144
#define NTHREADS  512                        // 16 warps: 2 (M) x 8 (N), warp tile 64x32
#define TILES_PER_BATCH (NSEQ / 128)         // 512
#define NCHUNK 4                             // K chunks of 64

// ---------------- SMEM map (dynamic, padded rows, NO swizzle) ----------------
// Row stride 144 bytes (= 128 data + 16 pad). 144 % 16 == 0 keeps ldmatrix
// addresses 16B aligned; consecutive rows step banks by +4, so the 8 rows of
// one ldmatrix phase cover all 32 banks exactly once (conflict-free).
#define ROWB  144
#define SM_FS   0u          // 256 floats
#define SM_PH   1024u       // 256 floats
#define SM_A    4096u       // 2 x (128*144 = 18432)
#define A_BUF   18432u
#define SM_B    40960u      // 4 x (256*144 = 36864)
#define B_BUF   36864u
#define SMEM_TOTAL 188416

__device__ __align__(16) __half g_W[NB * COUT * CIN];   // 2 MB scratch (W' fp16)

// ---------------- helpers ----------------
__device__ __forceinline__ uint32_t smem_u32(const void* p) {
    uint32_t a;
    asm("{ .reg .u64 t; cvta.to.shared.u64 t, %1; cvt.u32.u64 %0, t; }" : "=r"(a) : "l"(p));
    return a;
}

__device__ __forceinline__ void ldsm4(uint32_t& r0, uint32_t& r1, uint32_t& r2, uint32_t& r3,
                                      uint32_t addr) {
    asm volatile("ldmatrix.sync.aligned.m8n8.x4.shared.b16 {%0,%1,%2,%3}, [%4];"
                 : "=r"(r0), "=r"(r1), "=r"(r2), "=r"(r3) : "r"(addr));
}

__device__ __forceinline__ void mma16816(float* d, uint32_t a0, uint32_t a1, uint32_t a2,
                                         uint32_t a3, uint32_t b0, uint32_t b1) {
    asm volatile(
        "mma.sync.aligned.m16n8k16.row.col.f32.f16.f16.f32 "
        "{%0,%1,%2,%3}, {%4,%5,%6,%7}, {%8,%9}, {%0,%1,%2,%3};"
        : "+f"(d[0]), "+f"(d[1]), "+f"(d[2]), "+f"(d[3])
        : "r"(a0), "r"(a1), "r"(a2), "r"(a3), "r"(b0), "r"(b1));
}

// ------------- prep: W'[b,o,i] = weight[o,i]*(sigmoid(L.R/sqrt(10))+0.5) -------------
__global__ void __launch_bounds__(CIN) fmm_prep(const float* __restrict__ freq,
                                               const float* __restrict__ weight) {
    int bo = blockIdx.x;
    int b = bo >> 8;
    int o = bo & 255;
    int i = threadIdx.x;
    __shared__ float lsh[RANK];
    const float* fb = freq + (size_t)b * (RANK * (CIN + COUT));
    if (i < RANK) lsh[i] = fb[o * RANK + i];
    __syncthreads();
    const float* right = fb + COUT * RANK;   // [RANK, CIN]
    float acc = 0.f;
#pragma unroll
    for (int r = 0; r < RANK; r++) acc = fmaf(lsh[r], right[r * CIN + i], acc);
    acc *= 0.31622776601683794f;             // 1/sqrt(10)
    float sig = 1.0f / (1.0f + __expf(-acc));
    float w = weight[o * CIN + i] * (sig + 0.5f);
    g_W[(size_t)(b * COUT + o) * CIN + i] = __float2half_rn(w);
}

// ------------- main: persistent batched fp16 HMMA GEMM + sin epilogue -------------
__global__ void __launch_bounds__(NTHREADS, 1)
fmm_main(const float* __restrict__ x,
         const float* __restrict__ phase_shift,
         float* __restrict__ out) {
    extern __shared__ __align__(1024) char smem[];
    uint32_t sb = smem_u32(smem);
    int tid  = threadIdx.x;
    int wid  = tid >> 5;
    int lane = tid & 31;
    int wm   = wid >> 3;        // 0..1   (M direction, 64 rows each)
    int wn   = wid & 7;         // 0..7   (N direction, 32 cols each)

    int cta = blockIdx.x;
    int b   = cta / CTAS_PER_BATCH;
    int sub = cta % CTAS_PER_BATCH;

    // per-batch sin params
    if (tid < COUT) {
        float f = phase_shift[(size_t)b * (2 * COUT) + tid];
        float p = (phase_shift[(size_t)b * (2 * COUT) + COUT + tid] - 30.0f) * (1.0f / 15.0f);
        *(float*)(smem + SM_FS + tid * 4) = f;
        *(float*)(smem + SM_PH + tid * 4) = p;
    }

    // B = W' fp16 into padded SMEM: 4 K-chunks, each [256 rows(n) x 64 halves(k)]
    {
        const __half* Wb = g_W + (size_t)b * COUT * CIN;
        for (int it = tid; it < 8192; it += NTHREADS) {
            int o = it >> 5;                  // 0..255 (n)
            int i = (it & 31) * 8;            // 0..248 (k), 8 halves
            uint4 v = *reinterpret_cast<const uint4*>(Wb + (size_t)o * CIN + i);
            int c  = i >> 6;
            int kk = i & 63;
            uint32_t off = SM_B + (uint32_t)c * B_BUF + (uint32_t)o * ROWB + (uint32_t)kk * 2;
            *reinterpret_cast<uint4*>(smem + off) = v;
        }
    }
    __syncthreads();

    // ldmatrix lane address components
    int row16 = lane & 15;
    int koff  = (lane >> 4) << 3;             // 0 or 8 (halves)

    float4 stage[4];                          // staged fp32 x loads for next chunk

    auto ldg_chunk = [&](int t, int c) {
        const float* src = x + ((size_t)b * NSEQ + (size_t)t * 128) * CIN + c * 64;
#pragma unroll
        for (int j = 0; j < 4; j++) {
            int v  = j * NTHREADS + tid;      // 0..2047
            int m  = v >> 4;                  // row 0..127
            int k4 = (v & 15) * 4;            // 0..60
            stage[j] = __ldcs(reinterpret_cast<const float4*>(src + (size_t)m * CIN + k4));
        }
    };

    // preload first chunk
    ldg_chunk(sub, 0);

    for (int t = sub; t < TILES_PER_BATCH; t += CTAS_PER_BATCH) {
        float acc[4][4][4];
#pragma unroll
        for (int mi = 0; mi < 4; mi++)
#pragma unroll
            for (int ni = 0; ni < 4; ni++)
#pragma unroll
                for (int q = 0; q < 4; q++) acc[mi][ni][q] = 0.f;

#pragma unroll 1
        for (int c = 0; c < NCHUNK; c++) {
            // convert staged fp32 -> fp16, store into A buffer c&1
            uint32_t abase = SM_A + (uint32_t)(c & 1) * A_BUF;
#pragma unroll
            for (int j = 0; j < 4; j++) {
                int v  = j * NTHREADS + tid;
                int m  = v >> 4;
                int k4 = (v & 15) * 4;
                __half2 h0 = __floats2half2_rn(stage[j].x, stage[j].y);
                __half2 h1 = __floats2half2_rn(stage[j].z, stage[j].w);
                uint2 pkt;
                pkt.x = *reinterpret_cast<uint32_t*>(&h0);
                pkt.y = *reinterpret_cast<uint32_t*>(&h1);
                uint32_t off = abase + (uint32_t)m * ROWB + (uint32_t)k4 * 2;
                *reinterpret_cast<uint2*>(smem + off) = pkt;
            }
            __syncthreads();   // single barrier per chunk (A double-buffer makes this safe)

            // prefetch next chunk (possibly next tile's chunk 0)
            {
                int nc = c + 1, nt = t;
                if (nc == NCHUNK) { nc = 0; nt = t + CTAS_PER_BATCH; }
                if (nt < TILES_PER_BATCH) ldg_chunk(nt, nc);
            }

            // compute this chunk: 4 k16 steps
            uint32_t a_sb = sb + abase;
            uint32_t b_sb = sb + SM_B + (uint32_t)c * B_BUF;
#pragma unroll
            for (int ks = 0; ks < 4; ks++) {
                uint32_t a[4][4], bf[2][4];
                uint32_t kb = (uint32_t)((ks * 16 + koff) * 2);
#pragma unroll
                for (int mi = 0; mi < 4; mi++) {
                    uint32_t ad = a_sb + (uint32_t)(wm * 64 + mi * 16 + row16) * ROWB + kb;
                    ldsm4(a[mi][0], a[mi][1], a[mi][2], a[mi][3], ad);
                }
#pragma unroll
                for (int ng = 0; ng < 2; ng++) {
                    uint32_t bd = b_sb + (uint32_t)(wn * 32 + ng * 16 + row16) * ROWB + kb;
                    ldsm4(bf[ng][0], bf[ng][1], bf[ng][2], bf[ng][3], bd);
                }
#pragma unroll
                for (int mi = 0; mi < 4; mi++)
#pragma unroll
                    for (int ni = 0; ni < 4; ni++) {
                        int ng = ni >> 1;
                        uint32_t b0, b1;
                        if ((ni & 1) == 0) { b0 = bf[ng][0]; b1 = bf[ng][2]; }
                        else               { b0 = bf[ng][1]; b1 = bf[ng][3]; }
                        mma16816(acc[mi][ni], a[mi][0], a[mi][1], a[mi][2], a[mi][3], b0, b1);
                    }
            }
        }

        // -------- sin epilogue straight from fragments --------
        size_t rowbase = (size_t)b * NSEQ + (size_t)t * 128;
#pragma unroll
        for (int ni = 0; ni < 4; ni++) {
            int col = wn * 32 + ni * 8 + (lane & 3) * 2;
            float2 fs2 = *(float2*)(smem + SM_FS + col * 4);
            float2 ph2 = *(float2*)(smem + SM_PH + col * 4);
#pragma unroll
            for (int mi = 0; mi < 4; mi++) {
                int r0 = wm * 64 + mi * 16 + (lane >> 2);
                float2 o0, o1;
                o0.x = __sinf(fmaf(fs2.x, acc[mi][ni][0], ph2.x));
                o0.y = __sinf(fmaf(fs2.y, acc[mi][ni][1], ph2.y));
                o1.x = __sinf(fmaf(fs2.x, acc[mi][ni][2], ph2.x));
                o1.y = __sinf(fmaf(fs2.y, acc[mi][ni][3], ph2.y));
                __stcs(reinterpret_cast<float2*>(out + (rowbase + r0) * COUT + col), o0);
                __stcs(reinterpret_cast<float2*>(out + (rowbase + r0 + 8) * COUT + col), o1);
            }
        }
    }
}

extern "C" void kernel_launch(void* const* d_in, const int* in_sizes, int n_in,
                              void* d_out, int out_size) {
    const float* x    = (const float*)d_in[0];
    const float* freq = (const float*)d_in[1];
    const float* ps   = (const float*)d_in[2];
    const float* w    = (const float*)d_in[3];
    float* out = (float*)d_out;

    cudaFuncSetAttribute(fmm_main, cudaFuncAttributeMaxDynamicSharedMemorySize, SMEM_TOTAL);

    fmm_prep<<<NB * COUT, CIN>>>(freq, w);
    fmm_main<<<GRID_MAIN, NTHREADS, SMEM_TOTAL>>>(x, ps, out);
}

// round 13
// speedup vs baseline: 1.1163x; 1.0924x over previous
#include <cuda_runtime.h>
#include <cuda_fp16.h>
#include <cstdint>

// ---------------- problem constants ----------------
#define NB    16
#define NSEQ  65536
#define CIN   256
#define COUT  256
#define RANK  10

#define CTAS_PER_BATCH 9
#define GRID_MAIN (NB * CTAS_PER_BATCH)     // 144
#define NTHREADS  512                        // 2 groups x 8 warps; warp tile 64x32
#define TILES_PER_BATCH (NSEQ / 128)         // 512
#define NCHUNK 4                             // K chunks of 64

// ---------------- SMEM map (dynamic, padded rows, NO swizzle) ----------------
// Row stride 144 bytes (128 data + 16 pad): ldmatrix addresses stay 16B
// aligned; consecutive rows step banks by +4 so each 8-row ldmatrix phase
// covers all 32 banks once (conflict-free).
#define ROWB  144
#define SM_FS   0u          // 256 floats
#define SM_PH   1024u       // 256 floats
#define SM_A    4096u       // 2 groups x 2 bufs x (64*144 = 9216)
#define A_G     9216u
#define SM_B    40960u      // 4 chunks x (256*144 = 36864)
#define B_BUF   36864u
#define SMEM_TOTAL 188416

__device__ __align__(16) __half g_W[NB * COUT * CIN];   // 2 MB scratch (W' fp16)

// ---------------- helpers ----------------
__device__ __forceinline__ uint32_t smem_u32(const void* p) {
    uint32_t a;
    asm("{ .reg .u64 t; cvta.to.shared.u64 t, %1; cvt.u32.u64 %0, t; }" : "=r"(a) : "l"(p));
    return a;
}

__device__ __forceinline__ void ldsm4(uint32_t& r0, uint32_t& r1, uint32_t& r2, uint32_t& r3,
                                      uint32_t addr) {
    asm volatile("ldmatrix.sync.aligned.m8n8.x4.shared.b16 {%0,%1,%2,%3}, [%4];"
                 : "=r"(r0), "=r"(r1), "=r"(r2), "=r"(r3) : "r"(addr));
}

__device__ __forceinline__ void mma16816(float* d, uint32_t a0, uint32_t a1, uint32_t a2,
                                         uint32_t a3, uint32_t b0, uint32_t b1) {
    asm volatile(
        "mma.sync.aligned.m16n8k16.row.col.f32.f16.f16.f32 "
        "{%0,%1,%2,%3}, {%4,%5,%6,%7}, {%8,%9}, {%0,%1,%2,%3};"
        : "+f"(d[0]), "+f"(d[1]), "+f"(d[2]), "+f"(d[3])
        : "r"(a0), "r"(a1), "r"(a2), "r"(a3), "r"(b0), "r"(b1));
}

__device__ __forceinline__ void group_bar(int group) {
    asm volatile("bar.sync %0, 256;" :: "r"(group + 1) : "memory");
}

// ------------- prep: W'[b,o,i] = weight[o,i]*(sigmoid(L.R/sqrt(10))+0.5) -------------
__global__ void __launch_bounds__(CIN) fmm_prep(const float* __restrict__ freq,
                                               const float* __restrict__ weight) {
    int bo = blockIdx.x;
    int b = bo >> 8;
    int o = bo & 255;
    int i = threadIdx.x;
    __shared__ float lsh[RANK];
    const float* fb = freq + (size_t)b * (RANK * (CIN + COUT));
    if (i < RANK) lsh[i] = fb[o * RANK + i];
    __syncthreads();
    const float* right = fb + COUT * RANK;   // [RANK, CIN]
    float acc = 0.f;
#pragma unroll
    for (int r = 0; r < RANK; r++) acc = fmaf(lsh[r], right[r * CIN + i], acc);
    acc *= 0.31622776601683794f;             // 1/sqrt(10)
    float sig = 1.0f / (1.0f + __expf(-acc));
    float w = weight[o * CIN + i] * (sig + 0.5f);
    g_W[(size_t)(b * COUT + o) * CIN + i] = __float2half_rn(w);
}

// ------------- main: persistent batched fp16 HMMA GEMM + sin epilogue -------------
// Two independent 8-warp groups per CTA, each owning a 64-row M-half with its
// own A double-buffer and named barrier, so their convert/MMA/epilogue phases
// interleave instead of bulk-synchronizing the whole SM.
__global__ void __launch_bounds__(NTHREADS, 1)
fmm_main(const float* __restrict__ x,
         const float* __restrict__ phase_shift,
         float* __restrict__ out) {
    extern __shared__ __align__(1024) char smem[];
    uint32_t sb = smem_u32(smem);
    int tid   = threadIdx.x;
    int wid   = tid >> 5;
    int lane  = tid & 31;
    int group = wid >> 3;       // 0..1 (M halves of 64 rows)
    int gtid  = tid & 255;      // thread id within group
    int wn    = wid & 7;        // 0..7 (N direction, 32 cols each)

    int cta = blockIdx.x;
    int b   = cta / CTAS_PER_BATCH;
    int sub = cta % CTAS_PER_BATCH;

    // per-batch sin params
    if (tid < COUT) {
        float f = phase_shift[(size_t)b * (2 * COUT) + tid];
        float p = (phase_shift[(size_t)b * (2 * COUT) + COUT + tid] - 30.0f) * (1.0f / 15.0f);
        *(float*)(smem + SM_FS + tid * 4) = f;
        *(float*)(smem + SM_PH + tid * 4) = p;
    }

    // B = W' fp16 into padded SMEM: 4 K-chunks, each [256 rows(n) x 64 halves(k)]
    {
        const __half* Wb = g_W + (size_t)b * COUT * CIN;
        for (int it = tid; it < 8192; it += NTHREADS) {
            int o = it >> 5;                  // 0..255 (n)
            int i = (it & 31) * 8;            // 0..248 (k), 8 halves
            uint4 v = *reinterpret_cast<const uint4*>(Wb + (size_t)o * CIN + i);
            int c  = i >> 6;
            int kk = i & 63;
            uint32_t off = SM_B + (uint32_t)c * B_BUF + (uint32_t)o * ROWB + (uint32_t)kk * 2;
            *reinterpret_cast<uint4*>(smem + off) = v;
        }
    }
    __syncthreads();    // B + FS/PH visible to all; groups free-run after this

    // ldmatrix lane address components
    int row16 = lane & 15;
    int koff  = (lane >> 4) << 3;             // 0 or 8 (halves)

    uint32_t a_area = SM_A + (uint32_t)group * (2 * A_G);

    float4 stage[4];                          // staged fp32 x loads for next chunk

    // group's 64-row slice of tile t, chunk c -> stage regs
    auto ldg_chunk = [&](int t, int c) {
        const float* src = x + ((size_t)b * NSEQ + (size_t)t * 128 + group * 64) * CIN + c * 64;
#pragma unroll
        for (int j = 0; j < 4; j++) {
            int v  = j * 256 + gtid;          // 0..1023
            int m  = v >> 4;                  // row 0..63
            int k4 = (v & 15) * 4;            // 0..60
            stage[j] = __ldcs(reinterpret_cast<const float4*>(src + (size_t)m * CIN + k4));
        }
    };

    // preload first chunk
    ldg_chunk(sub, 0);

    for (int t = sub; t < TILES_PER_BATCH; t += CTAS_PER_BATCH) {
        float acc[4][4][4];
#pragma unroll
        for (int mi = 0; mi < 4; mi++)
#pragma unroll
            for (int ni = 0; ni < 4; ni++)
#pragma unroll
                for (int q = 0; q < 4; q++) acc[mi][ni][q] = 0.f;

#pragma unroll 1
        for (int c = 0; c < NCHUNK; c++) {
            // convert staged fp32 -> fp16 into group's A buffer c&1
            uint32_t abase = a_area + (uint32_t)(c & 1) * A_G;
#pragma unroll
            for (int j = 0; j < 4; j++) {
                int v  = j * 256 + gtid;
                int m  = v >> 4;
                int k4 = (v & 15) * 4;
                __half2 h0 = __floats2half2_rn(stage[j].x, stage[j].y);
                __half2 h1 = __floats2half2_rn(stage[j].z, stage[j].w);
                uint2 pkt;
                pkt.x = *reinterpret_cast<uint32_t*>(&h0);
                pkt.y = *reinterpret_cast<uint32_t*>(&h1);
                uint32_t off = abase + (uint32_t)m * ROWB + (uint32_t)k4 * 2;
                *reinterpret_cast<uint2*>(smem + off) = pkt;
            }
            group_bar(group);   // one barrier per chunk, group-scoped

            // prefetch next chunk (possibly next tile's chunk 0)
            {
                int nc = c + 1, nt = t;
                if (nc == NCHUNK) { nc = 0; nt = t + CTAS_PER_BATCH; }
                if (nt < TILES_PER_BATCH) ldg_chunk(nt, nc);
            }

            // compute this chunk: 4 k16 steps
            uint32_t a_sb = sb + abase;
            uint32_t b_sb = sb + SM_B + (uint32_t)c * B_BUF;
#pragma unroll
            for (int ks = 0; ks < 4; ks++) {
                uint32_t a[4][4], bf[2][4];
                uint32_t kb = (uint32_t)((ks * 16 + koff) * 2);
#pragma unroll
                for (int mi = 0; mi < 4; mi++) {
                    uint32_t ad = a_sb + (uint32_t)(mi * 16 + row16) * ROWB + kb;
                    ldsm4(a[mi][0], a[mi][1], a[mi][2], a[mi][3], ad);
                }
#pragma unroll
                for (int ng = 0; ng < 2; ng++) {
                    uint32_t bd = b_sb + (uint32_t)(wn * 32 + ng * 16 + row16) * ROWB + kb;
                    ldsm4(bf[ng][0], bf[ng][1], bf[ng][2], bf[ng][3], bd);
                }
#pragma unroll
                for (int mi = 0; mi < 4; mi++)
#pragma unroll
                    for (int ni = 0; ni < 4; ni++) {
                        int ng = ni >> 1;
                        uint32_t b0, b1;
                        if ((ni & 1) == 0) { b0 = bf[ng][0]; b1 = bf[ng][2]; }
                        else               { b0 = bf[ng][1]; b1 = bf[ng][3]; }
                        mma16816(acc[mi][ni], a[mi][0], a[mi][1], a[mi][2], a[mi][3], b0, b1);
                    }
            }
        }

        // -------- sin epilogue straight from fragments (group's 64 rows) --------
        size_t rowbase = (size_t)b * NSEQ + (size_t)t * 128 + group * 64;
#pragma unroll
        for (int ni = 0; ni < 4; ni++) {
            int col = wn * 32 + ni * 8 + (lane & 3) * 2;
            float2 fs2 = *(float2*)(smem + SM_FS + col * 4);
            float2 ph2 = *(float2*)(smem + SM_PH + col * 4);
#pragma unroll
            for (int mi = 0; mi < 4; mi++) {
                int r0 = mi * 16 + (lane >> 2);
                float2 o0, o1;
                o0.x = __sinf(fmaf(fs2.x, acc[mi][ni][0], ph2.x));
                o0.y = __sinf(fmaf(fs2.y, acc[mi][ni][1], ph2.y));
                o1.x = __sinf(fmaf(fs2.x, acc[mi][ni][2], ph2.x));
                o1.y = __sinf(fmaf(fs2.y, acc[mi][ni][3], ph2.y));
                __stcs(reinterpret_cast<float2*>(out + (rowbase + r0) * COUT + col), o0);
                __stcs(reinterpret_cast<float2*>(out + (rowbase + r0 + 8) * COUT + col), o1);
            }
        }
    }
}

extern "C" void kernel_launch(void* const* d_in, const int* in_sizes, int n_in,
                              void* d_out, int out_size) {
    const float* x    = (const float*)d_in[0];
    const float* freq = (const float*)d_in[1];
    const float* ps   = (const float*)d_in[2];
    const float* w    = (const float*)d_in[3];
    float* out = (float*)d_out;

    cudaFuncSetAttribute(fmm_main, cudaFuncAttributeMaxDynamicSharedMemorySize, SMEM_TOTAL);

    fmm_prep<<<NB * COUT, CIN>>>(freq, w);
    fmm_main<<<GRID_MAIN, NTHREADS, SMEM_TOTAL>>>(x, ps, out);
}

// round 14
// speedup vs baseline: 1.2074x; 1.0817x over previous
#include <cuda_runtime.h>
#include <cuda_fp16.h>
#include <cstdint>

// ---------------- problem constants ----------------
#define NB    16
#define NSEQ  65536
#define CIN   256
#define COUT  256
#define RANK  10

#define GRID_MAIN 148                        // persistent, global tile partition
#define NTHREADS  512                        // 4 groups x 4 warps; warp tile 32x64
#define TILES_PER_BATCH (NSEQ / 128)         // 512
#define TOTAL_TILES (NB * TILES_PER_BATCH)   // 8192
#define NCHUNK 4                             // K chunks of 64

// ---------------- SMEM map (dynamic, padded rows, NO swizzle) ----------------
// Row stride 144 bytes (128 data + 16 pad): ldmatrix addresses stay 16B
// aligned; consecutive rows step banks by +4 so each 8-row ldmatrix phase
// covers all 32 banks once (conflict-free).
#define ROWB  144
#define SM_FS   0u          // 256 floats
#define SM_PH   1024u       // 256 floats
#define SM_A    4096u       // 4 groups x 2 bufs x (32*144 = 4608)
#define A_G     4608u
#define SM_B    40960u      // 4 chunks x (256*144 = 36864)
#define B_BUF   36864u
#define SMEM_TOTAL 188416

__device__ __align__(16) __half g_W[NB * COUT * CIN];   // 2 MB scratch (W' fp16)

// ---------------- helpers ----------------
__device__ __forceinline__ uint32_t smem_u32(const void* p) {
    uint32_t a;
    asm("{ .reg .u64 t; cvta.to.shared.u64 t, %1; cvt.u32.u64 %0, t; }" : "=r"(a) : "l"(p));
    return a;
}

__device__ __forceinline__ void ldsm4(uint32_t& r0, uint32_t& r1, uint32_t& r2, uint32_t& r3,
                                      uint32_t addr) {
    asm volatile("ldmatrix.sync.aligned.m8n8.x4.shared.b16 {%0,%1,%2,%3}, [%4];"
                 : "=r"(r0), "=r"(r1), "=r"(r2), "=r"(r3) : "r"(addr));
}

__device__ __forceinline__ void mma16816(float* d, uint32_t a0, uint32_t a1, uint32_t a2,
                                         uint32_t a3, uint32_t b0, uint32_t b1) {
    asm volatile(
        "mma.sync.aligned.m16n8k16.row.col.f32.f16.f16.f32 "
        "{%0,%1,%2,%3}, {%4,%5,%6,%7}, {%8,%9}, {%0,%1,%2,%3};"
        : "+f"(d[0]), "+f"(d[1]), "+f"(d[2]), "+f"(d[3])
        : "r"(a0), "r"(a1), "r"(a2), "r"(a3), "r"(b0), "r"(b1));
}

__device__ __forceinline__ void group_bar(int group) {
    asm volatile("bar.sync %0, 128;" :: "r"(group + 1) : "memory");
}

// ------------- prep: W'[b,o,i] = weight[o,i]*(sigmoid(L.R/sqrt(10))+0.5) -------------
__global__ void __launch_bounds__(CIN) fmm_prep(const float* __restrict__ freq,
                                               const float* __restrict__ weight) {
    int bo = blockIdx.x;
    int b = bo >> 8;
    int o = bo & 255;
    int i = threadIdx.x;
    __shared__ float lsh[RANK];
    const float* fb = freq + (size_t)b * (RANK * (CIN + COUT));
    if (i < RANK) lsh[i] = fb[o * RANK + i];
    __syncthreads();
    const float* right = fb + COUT * RANK;   // [RANK, CIN]
    float acc = 0.f;
#pragma unroll
    for (int r = 0; r < RANK; r++) acc = fmaf(lsh[r], right[r * CIN + i], acc);
    acc *= 0.31622776601683794f;             // 1/sqrt(10)
    float sig = 1.0f / (1.0f + __expf(-acc));
    float w = weight[o * CIN + i] * (sig + 0.5f);
    g_W[(size_t)(b * COUT + o) * CIN + i] = __float2half_rn(w);
}

// ------------- main: persistent batched fp16 HMMA GEMM + sin epilogue -------------
// 148 persistent CTAs over a global tile index (x/out rows are g*128 since the
// batch dims are contiguous). Four independent 4-warp groups per CTA, each
// owning a 32-row M-slice with its own A double-buffer and named barrier, so
// convert/MMA/epilogue phases of the groups interleave on the SM.
__global__ void __launch_bounds__(NTHREADS, 1)
fmm_main(const float* __restrict__ x,
         const float* __restrict__ phase_shift,
         float* __restrict__ out) {
    extern __shared__ __align__(1024) char smem[];
    uint32_t sb = smem_u32(smem);
    int tid   = threadIdx.x;
    int wid   = tid >> 5;
    int lane  = tid & 31;
    int group = wid >> 2;       // 0..3 (M slices of 32 rows)
    int gtid  = tid & 127;      // thread id within group
    int wn    = wid & 3;        // 0..3 (N direction, 64 cols each)

    // global tile range for this CTA: base 55, first 52 CTAs get one extra
    int cta = blockIdx.x;
    int g0  = cta * 55 + (cta < 52 ? cta : 52);
    int g1  = g0 + 55 + (cta < 52 ? 1 : 0);

    // ldmatrix lane address components
    int row16 = lane & 15;
    int koff  = (lane >> 4) << 3;             // 0 or 8 (halves)

    uint32_t a_area = SM_A + (uint32_t)group * (2 * A_G);

    float4 stage[4];                          // staged fp32 x loads for next chunk

    // group's 32-row slice of global tile g, chunk c -> stage regs
    auto ldg_chunk = [&](int g, int c) {
        const float* src = x + ((size_t)g * 128 + group * 32) * CIN + c * 64;
#pragma unroll
        for (int j = 0; j < 4; j++) {
            int v  = j * 128 + gtid;          // 0..511
            int m  = v >> 4;                  // row 0..31
            int k4 = (v & 15) * 4;            // 0..60
            stage[j] = __ldcs(reinterpret_cast<const float4*>(src + (size_t)m * CIN + k4));
        }
    };

    // load batch-resident B (W') + sin params; caller wraps with __syncthreads
    auto load_batch = [&](int b) {
        if (tid < COUT) {
            float f = phase_shift[(size_t)b * (2 * COUT) + tid];
            float p = (phase_shift[(size_t)b * (2 * COUT) + COUT + tid] - 30.0f) * (1.0f / 15.0f);
            *(float*)(smem + SM_FS + tid * 4) = f;
            *(float*)(smem + SM_PH + tid * 4) = p;
        }
        const __half* Wb = g_W + (size_t)b * COUT * CIN;
        for (int it = tid; it < 8192; it += NTHREADS) {
            int o = it >> 5;                  // 0..255 (n)
            int i = (it & 31) * 8;            // 0..248 (k), 8 halves
            uint4 v = *reinterpret_cast<const uint4*>(Wb + (size_t)o * CIN + i);
            int c  = i >> 6;
            int kk = i & 63;
            uint32_t off = SM_B + (uint32_t)c * B_BUF + (uint32_t)o * ROWB + (uint32_t)kk * 2;
            *reinterpret_cast<uint4*>(smem + off) = v;
        }
    };

    // preload first chunk (x only, batch-independent addressing)
    ldg_chunk(g0, 0);

    int cur_b = -1;
    for (int g = g0; g < g1; ++g) {
        int b = g >> 9;                       // g / TILES_PER_BATCH
        if (b != cur_b) {
            __syncthreads();                  // all groups done reading old B
            load_batch(b);
            __syncthreads();
            cur_b = b;
        }

        float acc[2][8][4];
#pragma unroll
        for (int mi = 0; mi < 2; mi++)
#pragma unroll
            for (int ni = 0; ni < 8; ni++)
#pragma unroll
                for (int q = 0; q < 4; q++) acc[mi][ni][q] = 0.f;

#pragma unroll 1
        for (int c = 0; c < NCHUNK; c++) {
            // convert staged fp32 -> fp16 into group's A buffer c&1
            uint32_t abase = a_area + (uint32_t)(c & 1) * A_G;
#pragma unroll
            for (int j = 0; j < 4; j++) {
                int v  = j * 128 + gtid;
                int m  = v >> 4;
                int k4 = (v & 15) * 4;
                __half2 h0 = __floats2half2_rn(stage[j].x, stage[j].y);
                __half2 h1 = __floats2half2_rn(stage[j].z, stage[j].w);
                uint2 pkt;
                pkt.x = *reinterpret_cast<uint32_t*>(&h0);
                pkt.y = *reinterpret_cast<uint32_t*>(&h1);
                uint32_t off = abase + (uint32_t)m * ROWB + (uint32_t)k4 * 2;
                *reinterpret_cast<uint2*>(smem + off) = pkt;
            }

            // prefetch next chunk BEFORE the barrier (no SMEM dependence):
            // its DRAM latency overlaps the barrier drain + compute
            {
                int nc = c + 1, ng = g;
                if (nc == NCHUNK) { nc = 0; ng = g + 1; }
                if (ng < g1) ldg_chunk(ng, nc);
            }

            group_bar(group);   // one barrier per chunk, group-scoped

            // compute this chunk: 4 k16 steps
            uint32_t a_sb = sb + abase;
            uint32_t b_sb = sb + SM_B + (uint32_t)c * B_BUF;
#pragma unroll
            for (int ks = 0; ks < 4; ks++) {
                uint32_t a[2][4], bf[4][4];
                uint32_t kb = (uint32_t)((ks * 16 + koff) * 2);
#pragma unroll
                for (int mi = 0; mi < 2; mi++) {
                    uint32_t ad = a_sb + (uint32_t)(mi * 16 + row16) * ROWB + kb;
                    ldsm4(a[mi][0], a[mi][1], a[mi][2], a[mi][3], ad);
                }
#pragma unroll
                for (int ng2 = 0; ng2 < 4; ng2++) {
                    uint32_t bd = b_sb + (uint32_t)(wn * 64 + ng2 * 16 + row16) * ROWB + kb;
                    ldsm4(bf[ng2][0], bf[ng2][1], bf[ng2][2], bf[ng2][3], bd);
                }
#pragma unroll
                for (int mi = 0; mi < 2; mi++)
#pragma unroll
                    for (int ni = 0; ni < 8; ni++) {
                        int ng2 = ni >> 1;
                        uint32_t b0, b1;
                        if ((ni & 1) == 0) { b0 = bf[ng2][0]; b1 = bf[ng2][2]; }
                        else                { b0 = bf[ng2][1]; b1 = bf[ng2][3]; }
                        mma16816(acc[mi][ni], a[mi][0], a[mi][1], a[mi][2], a[mi][3], b0, b1);
                    }
            }
        }

        // -------- sin epilogue straight from fragments (group's 32 rows) --------
        size_t rowbase = (size_t)g * 128 + group * 32;
#pragma unroll
        for (int ni = 0; ni < 8; ni++) {
            int col = wn * 64 + ni * 8 + (lane & 3) * 2;
            float2 fs2 = *(float2*)(smem + SM_FS + col * 4);
            float2 ph2 = *(float2*)(smem + SM_PH + col * 4);
#pragma unroll
            for (int mi = 0; mi < 2; mi++) {
                int r0 = mi * 16 + (lane >> 2);
                float2 o0, o1;
                o0.x = __sinf(fmaf(fs2.x, acc[mi][ni][0], ph2.x));
                o0.y = __sinf(fmaf(fs2.y, acc[mi][ni][1], ph2.y));
                o1.x = __sinf(fmaf(fs2.x, acc[mi][ni][2], ph2.x));
                o1.y = __sinf(fmaf(fs2.y, acc[mi][ni][3], ph2.y));
                __stcs(reinterpret_cast<float2*>(out + (rowbase + r0) * COUT + col), o0);
                __stcs(reinterpret_cast<float2*>(out + (rowbase + r0 + 8) * COUT + col), o1);
            }
        }
    }
}

extern "C" void kernel_launch(void* const* d_in, const int* in_sizes, int n_in,
                              void* d_out, int out_size) {
    const float* x    = (const float*)d_in[0];
    const float* freq = (const float*)d_in[1];
    const float* ps   = (const float*)d_in[2];
    const float* w    = (const float*)d_in[3];
    float* out = (float*)d_out;

    cudaFuncSetAttribute(fmm_main, cudaFuncAttributeMaxDynamicSharedMemorySize, SMEM_TOTAL);

    fmm_prep<<<NB * COUT, CIN>>>(freq, w);
    fmm_main<<<GRID_MAIN, NTHREADS, SMEM_TOTAL>>>(x, ps, out);
}